// round 14
// baseline (speedup 1.0000x reference)
#include <cuda_runtime.h>
#include <cuda_bf16.h>
#include <cuda_fp16.h>
#include <math.h>
#include <stdint.h>

// Problem constants
#define NN   50000
#define EE   800000
#define IND  256
#define HH   4
#define FF   64
#define HF   256
#define EFD  64
#define NT   8
#define SLOPE 0.2f

// ---------------- scratch ----------------------------------------------------
__device__ __half g_feat_h[NN * HF];          // fp16 feat (gather payload)
__device__ float g_el[NN * HH];
__device__ float g_er[NN * HH];
__device__ float g_ee[NT * HH];
__device__ int   g_srcs[EE];                  // CSR: src per slot
__device__ int   g_etp[EE];                   // CSR: etype per slot
__device__ int   g_eids[EE];                  // CSR: original edge id per slot
__device__ __nv_bfloat16 g_B1[IND * HF];
__device__ __nv_bfloat16 g_B2[IND * HF];
__device__ int   g_cnt[NN + 1];
__device__ int   g_off[NN + 1];
__device__ int   g_cursor[NN];
__device__ int   g_bsum[64];
__device__ int   g_bpre[65];

// ---------------- helpers -----------------------------------------------------
__device__ __forceinline__ uint32_t smem_u32(const void* p) {
    uint32_t a;
    asm("{ .reg .u64 t; cvta.to.shared.u64 t, %1; cvt.u32.u64 %0, t; }"
        : "=r"(a) : "l"(p));
    return a;
}
__device__ __forceinline__ void ldmatrix_x4(uint32_t* r, uint32_t addr) {
    asm volatile("ldmatrix.sync.aligned.m8n8.x4.shared.b16 {%0,%1,%2,%3}, [%4];"
                 : "=r"(r[0]), "=r"(r[1]), "=r"(r[2]), "=r"(r[3]) : "r"(addr));
}
__device__ __forceinline__ void ldmatrix_x4_t(uint32_t* r, uint32_t addr) {
    asm volatile("ldmatrix.sync.aligned.m8n8.x4.trans.shared.b16 {%0,%1,%2,%3}, [%4];"
                 : "=r"(r[0]), "=r"(r[1]), "=r"(r[2]), "=r"(r[3]) : "r"(addr));
}
__device__ __forceinline__ void mma_bf16(float* c, const uint32_t* a,
                                         uint32_t b0, uint32_t b1) {
    asm volatile(
        "mma.sync.aligned.m16n8k16.row.col.f32.bf16.bf16.f32 "
        "{%0,%1,%2,%3}, {%4,%5,%6,%7}, {%8,%9}, {%0,%1,%2,%3};"
        : "+f"(c[0]), "+f"(c[1]), "+f"(c[2]), "+f"(c[3])
        : "r"(a[0]), "r"(a[1]), "r"(a[2]), "r"(a[3]), "r"(b0), "r"(b1));
}
__device__ __forceinline__ uint32_t pack_hi(float a, float b) {
    return ((uint32_t)__bfloat16_as_ushort(__float2bfloat16_rn(b)) << 16) |
           (uint32_t)__bfloat16_as_ushort(__float2bfloat16_rn(a));
}
__device__ __forceinline__ uint32_t pack_lo(float a, float b) {
    float ar = a - __bfloat162float(__float2bfloat16_rn(a));
    float br = b - __bfloat162float(__float2bfloat16_rn(b));
    return ((uint32_t)__bfloat16_as_ushort(__float2bfloat16_rn(br)) << 16) |
           (uint32_t)__bfloat16_as_ushort(__float2bfloat16_rn(ar));
}

// ---------------- B pre-conversion ------------------------------------------
__global__ void convert_b_kernel(const float* __restrict__ Bw)
{
    int i = (blockIdx.x * blockDim.x + threadIdx.x) * 4;
    float4 v = *(const float4*)(Bw + i);
    float f[4] = { v.x, v.y, v.z, v.w };
#pragma unroll
    for (int q = 0; q < 4; q++) {
        __nv_bfloat16 h = __float2bfloat16_rn(f[q]);
        g_B1[i + q] = h;
        g_B2[i + q] = __float2bfloat16_rn(f[q] - __bfloat162float(h));
    }
}

// ---------------- bf16-split GEMM, double-buffered smem, fused el/er ---------
#define BM 128
#define BN 128
#define BK 32
#define AST 40
#define BST 136
#define STG_A1 0
#define STG_A2 10240
#define STG_B1 20480
#define STG_B2 29184
#define STG_SZ 37888
#define GEMM_SMEM (2 * STG_SZ)

__global__ void __launch_bounds__(256, 2)
gemm_mma_kernel(const float* __restrict__ A, __half* __restrict__ C,
                const float* __restrict__ attn_l, const float* __restrict__ attn_r,
                int M)
{
    extern __shared__ __align__(16) char dynsm[];

    const int tid  = threadIdx.x;
    const int lane = tid & 31;
    const int wid  = tid >> 5;
    const int m0 = blockIdx.x * BM;
    const int n0 = blockIdx.y * BN;

    const int wm = (wid & 1) * 64;
    const int wn = (wid >> 1) * 32;

    float acc[4][4][4];
#pragma unroll
    for (int i = 0; i < 4; i++)
#pragma unroll
        for (int j = 0; j < 4; j++)
#pragma unroll
            for (int r = 0; r < 4; r++) acc[i][j][r] = 0.f;

    const int a_row  = tid >> 1;
    const int a_colb = (tid & 1) * 16;
    const int a_gr   = m0 + a_row;
    const int b_kr  = tid >> 3;
    const int b_nb  = (tid & 7) * 16;

    const int mat  = lane >> 3;
    const int l8   = lane & 7;
    const int a_mrow = (mat & 1) * 8 + l8;
    const int a_koff = (mat >> 1) * 8;
    const int b_krow = (mat & 1) * 8 + l8;
    const int b_noff = (mat >> 1) * 8;

    const uint32_t sm0 = smem_u32(dynsm);

    float4 va[4];
    uint4 vbh[2], vbl[2];
    {
        if (a_gr < M) {
            const float4* p = (const float4*)(A + (size_t)a_gr * IND + a_colb);
#pragma unroll
            for (int q = 0; q < 4; q++) va[q] = p[q];
        } else {
#pragma unroll
            for (int q = 0; q < 4; q++) va[q] = make_float4(0, 0, 0, 0);
        }
        const uint4* p1 = (const uint4*)(g_B1 + (size_t)b_kr * HF + n0 + b_nb);
        const uint4* p2 = (const uint4*)(g_B2 + (size_t)b_kr * HF + n0 + b_nb);
        vbh[0] = p1[0]; vbh[1] = p1[1];
        vbl[0] = p2[0]; vbl[1] = p2[1];
    }

    for (int c = 0; c < IND / BK; c++) {
        char* stg = dynsm + (c & 1) * STG_SZ;
        {
            uint32_t hi[8], lo[8];
#pragma unroll
            for (int q = 0; q < 4; q++) {
                hi[2 * q]     = pack_hi(va[q].x, va[q].y);
                hi[2 * q + 1] = pack_hi(va[q].z, va[q].w);
                lo[2 * q]     = pack_lo(va[q].x, va[q].y);
                lo[2 * q + 1] = pack_lo(va[q].z, va[q].w);
            }
            char* d1 = stg + STG_A1 + (a_row * AST + a_colb) * 2;
            char* d2 = stg + STG_A2 + (a_row * AST + a_colb) * 2;
            ((uint4*)d1)[0] = make_uint4(hi[0], hi[1], hi[2], hi[3]);
            ((uint4*)d1)[1] = make_uint4(hi[4], hi[5], hi[6], hi[7]);
            ((uint4*)d2)[0] = make_uint4(lo[0], lo[1], lo[2], lo[3]);
            ((uint4*)d2)[1] = make_uint4(lo[4], lo[5], lo[6], lo[7]);
            char* e1 = stg + STG_B1 + (b_kr * BST + b_nb) * 2;
            char* e2 = stg + STG_B2 + (b_kr * BST + b_nb) * 2;
            ((uint4*)e1)[0] = vbh[0];
            ((uint4*)e1)[1] = vbh[1];
            ((uint4*)e2)[0] = vbl[0];
            ((uint4*)e2)[1] = vbl[1];
        }
        __syncthreads();

        if (c + 1 < IND / BK) {
            const int k0 = (c + 1) * BK;
            if (a_gr < M) {
                const float4* p = (const float4*)(A + (size_t)a_gr * IND + k0 + a_colb);
#pragma unroll
                for (int q = 0; q < 4; q++) va[q] = p[q];
            } else {
#pragma unroll
                for (int q = 0; q < 4; q++) va[q] = make_float4(0, 0, 0, 0);
            }
            const uint4* p1 = (const uint4*)(g_B1 + (size_t)(k0 + b_kr) * HF + n0 + b_nb);
            const uint4* p2 = (const uint4*)(g_B2 + (size_t)(k0 + b_kr) * HF + n0 + b_nb);
            vbh[0] = p1[0]; vbh[1] = p1[1];
            vbl[0] = p2[0]; vbl[1] = p2[1];
        }

        const uint32_t sa1 = sm0 + (c & 1) * STG_SZ + STG_A1;
        const uint32_t sa2 = sm0 + (c & 1) * STG_SZ + STG_A2;
        const uint32_t sb1 = sm0 + (c & 1) * STG_SZ + STG_B1;
        const uint32_t sb2 = sm0 + (c & 1) * STG_SZ + STG_B2;

#pragma unroll
        for (int kk = 0; kk < 2; kk++) {
            uint32_t a1[4][4], a2[4][4], b1[2][4], b2[2][4];
#pragma unroll
            for (int i = 0; i < 4; i++) {
                uint32_t off = ((wm + i * 16 + a_mrow) * AST + kk * 16 + a_koff) * 2;
                ldmatrix_x4(a1[i], sa1 + off);
                ldmatrix_x4(a2[i], sa2 + off);
            }
#pragma unroll
            for (int j2 = 0; j2 < 2; j2++) {
                uint32_t off = ((kk * 16 + b_krow) * BST + wn + j2 * 16 + b_noff) * 2;
                ldmatrix_x4_t(b1[j2], sb1 + off);
                ldmatrix_x4_t(b2[j2], sb2 + off);
            }
#pragma unroll
            for (int i = 0; i < 4; i++) {
#pragma unroll
                for (int j2 = 0; j2 < 2; j2++) {
                    mma_bf16(acc[i][2 * j2],     a1[i], b1[j2][0], b1[j2][1]);
                    mma_bf16(acc[i][2 * j2],     a1[i], b2[j2][0], b2[j2][1]);
                    mma_bf16(acc[i][2 * j2],     a2[i], b1[j2][0], b1[j2][1]);
                    mma_bf16(acc[i][2 * j2 + 1], a1[i], b1[j2][2], b1[j2][3]);
                    mma_bf16(acc[i][2 * j2 + 1], a1[i], b2[j2][2], b2[j2][3]);
                    mma_bf16(acc[i][2 * j2 + 1], a2[i], b1[j2][2], b1[j2][3]);
                }
            }
        }
    }

    // ---- epilogue: store C (fp16) + fused el/er (fp32)
    const int crow = lane >> 2;
    const int ccol = (lane & 3) * 2;

    float al[4][2], ar[4][2];
#pragma unroll
    for (int j = 0; j < 4; j++) {
        int c = n0 + wn + j * 8 + ccol;
        al[j][0] = attn_l[c];     al[j][1] = attn_l[c + 1];
        ar[j][0] = attn_r[c];     ar[j][1] = attn_r[c + 1];
    }
    const int head = (n0 + wn) >> 6;

#pragma unroll
    for (int i = 0; i < 4; i++) {
        int r0 = m0 + wm + i * 16 + crow;
        float pl0 = 0.f, pr0 = 0.f, pl1 = 0.f, pr1 = 0.f;
#pragma unroll
        for (int j = 0; j < 4; j++) {
            int c = n0 + wn + j * 8 + ccol;
            if (r0 < M)
                *(__half2*)(C + (size_t)r0 * HF + c) =
                    __floats2half2_rn(acc[i][j][0], acc[i][j][1]);
            if (r0 + 8 < M)
                *(__half2*)(C + (size_t)(r0 + 8) * HF + c) =
                    __floats2half2_rn(acc[i][j][2], acc[i][j][3]);
            pl0 += acc[i][j][0] * al[j][0] + acc[i][j][1] * al[j][1];
            pr0 += acc[i][j][0] * ar[j][0] + acc[i][j][1] * ar[j][1];
            pl1 += acc[i][j][2] * al[j][0] + acc[i][j][3] * al[j][1];
            pr1 += acc[i][j][2] * ar[j][0] + acc[i][j][3] * ar[j][1];
        }
#pragma unroll
        for (int o = 1; o <= 2; o <<= 1) {
            pl0 += __shfl_xor_sync(0xffffffffu, pl0, o);
            pr0 += __shfl_xor_sync(0xffffffffu, pr0, o);
            pl1 += __shfl_xor_sync(0xffffffffu, pl1, o);
            pr1 += __shfl_xor_sync(0xffffffffu, pr1, o);
        }
        if ((lane & 3) == 0) {
            if (r0 < M) {
                atomicAdd(&g_el[r0 * HH + head], pl0);
                atomicAdd(&g_er[r0 * HH + head], pr0);
            }
            if (r0 + 8 < M) {
                atomicAdd(&g_el[(r0 + 8) * HH + head], pl1);
                atomicAdd(&g_er[(r0 + 8) * HH + head], pr1);
            }
        }
    }
}

// ---------------- ee per etype ------------------------------------------------
__global__ void ee_kernel(const float* __restrict__ edge_emb,
                          const float* __restrict__ fc_e_w,
                          const float* __restrict__ attn_e)
{
    int t = threadIdx.x;
    if (t >= NT * HH) return;
    int tt = t >> 2, h = t & 3;
    float sum = 0.f;
    for (int e = 0; e < EFD; e++) {
        float ef = 0.f;
#pragma unroll 8
        for (int k = 0; k < EFD; k++)
            ef += edge_emb[tt * EFD + k] * fc_e_w[k * (HH * EFD) + h * EFD + e];
        sum += ef * attn_e[h * EFD + e];
    }
    g_ee[tt * HH + h] = sum;
}

// ---------------- CSR build ---------------------------------------------------
__global__ void count_kernel(const int* __restrict__ dst)
{
    int e = blockIdx.x * blockDim.x + threadIdx.x;
    if (e < EE) atomicAdd(&g_cnt[dst[e]], 1);
}

#define SCAN_B 1024
#define NSCAN ((NN + SCAN_B - 1) / SCAN_B)

__global__ void scan1_kernel()
{
    __shared__ int s[SCAN_B];
    int b = blockIdx.x, tid = threadIdx.x;
    int idx = b * SCAN_B + tid;
    int v = (idx < NN) ? g_cnt[idx] : 0;
    s[tid] = v;
    __syncthreads();
    for (int off = 1; off < SCAN_B; off <<= 1) {
        int tmp = (tid >= off) ? s[tid - off] : 0;
        __syncthreads();
        s[tid] += tmp;
        __syncthreads();
    }
    if (idx < NN) g_off[idx] = s[tid] - v;
    if (tid == SCAN_B - 1) g_bsum[b] = s[tid];
}

__global__ void scan2_kernel()
{
    if (threadIdx.x == 0) {
        int acc = 0;
        for (int b = 0; b < NSCAN; b++) { g_bpre[b] = acc; acc += g_bsum[b]; }
        g_bpre[NSCAN] = acc;
    }
}

__global__ void scan3_kernel()
{
    int idx = blockIdx.x * blockDim.x + threadIdx.x;
    if (idx < NN) {
        int v = g_off[idx] + g_bpre[idx >> 10];
        g_off[idx] = v;
        g_cursor[idx] = v;
    } else if (idx == NN) {
        g_off[NN] = g_bpre[NSCAN];
    }
}

// ---- scatter_ids: build CSR-ordered src/etype/eid (no scores; off crit path) --
__global__ void scatter_ids_kernel(const int* __restrict__ src,
                                   const int* __restrict__ dst,
                                   const int* __restrict__ etype)
{
    int e = blockIdx.x * blockDim.x + threadIdx.x;
    if (e >= EE) return;
    int dv = dst[e];
    int pos = atomicAdd(&g_cursor[dv], 1);
    g_eids[pos] = e;
    g_srcs[pos] = src[e];
    g_etp[pos]  = etype[e];
}

// ---------------- fused softmax + out_a + aggregation (warp per dst) ----------
__global__ void __launch_bounds__(256)
aggregate_kernel(float* __restrict__ out_rst, float* __restrict__ out_a)
{
    const int d    = blockIdx.x * 8 + (threadIdx.x >> 5);
    const int lane = threadIdx.x & 31;
    if (d >= NN) return;

    const int off = g_off[d];
    const int deg = g_off[d + 1] - off;
    const int hh  = lane >> 3;
    const int co  = lane * 8;

    float a[8];
#pragma unroll
    for (int q = 0; q < 8; q++) a[q] = 0.f;

    if (deg == 0) {
        float4* op = (float4*)(out_rst + (size_t)d * HF + co);
        op[0] = make_float4(0.f, 0.f, 0.f, 0.f);
        op[1] = make_float4(0.f, 0.f, 0.f, 0.f);
        return;
    }

    const float erh = g_er[d * HH + hh];

    // ---- pass 1: per-head softmax denominator (all lanes see all edges;
    //      the 8 lanes of a head group compute identical sums — no reduction)
    float s = 0.f;
    {
        int i = 0;
        for (; i + 4 <= deg; i += 4) {
            int sv0 = __ldg(&g_srcs[off + i]);
            int sv1 = __ldg(&g_srcs[off + i + 1]);
            int sv2 = __ldg(&g_srcs[off + i + 2]);
            int sv3 = __ldg(&g_srcs[off + i + 3]);
            int t0 = __ldg(&g_etp[off + i]);
            int t1 = __ldg(&g_etp[off + i + 1]);
            int t2 = __ldg(&g_etp[off + i + 2]);
            int t3 = __ldg(&g_etp[off + i + 3]);
            float x0 = __ldg(&g_el[sv0 * HH + hh]) + erh + __ldg(&g_ee[t0 * HH + hh]);
            float x1 = __ldg(&g_el[sv1 * HH + hh]) + erh + __ldg(&g_ee[t1 * HH + hh]);
            float x2 = __ldg(&g_el[sv2 * HH + hh]) + erh + __ldg(&g_ee[t2 * HH + hh]);
            float x3 = __ldg(&g_el[sv3 * HH + hh]) + erh + __ldg(&g_ee[t3 * HH + hh]);
            x0 = x0 > 0.f ? x0 : SLOPE * x0;
            x1 = x1 > 0.f ? x1 : SLOPE * x1;
            x2 = x2 > 0.f ? x2 : SLOPE * x2;
            x3 = x3 > 0.f ? x3 : SLOPE * x3;
            s += __expf(x0) + __expf(x1) + __expf(x2) + __expf(x3);
        }
        for (; i < deg; i++) {
            int sv = __ldg(&g_srcs[off + i]);
            int tp = __ldg(&g_etp[off + i]);
            float x = __ldg(&g_el[sv * HH + hh]) + erh + __ldg(&g_ee[tp * HH + hh]);
            x = x > 0.f ? x : SLOPE * x;
            s += __expf(x);
        }
    }
    const float rs = 1.f / s;

    // ---- pass 2: weights, out_a scatter, fp16 feat gather-accumulate
    for (int i = 0; i < deg; i++) {
        int sv = __ldg(&g_srcs[off + i]);
        int tp = __ldg(&g_etp[off + i]);
        float x = __ldg(&g_el[sv * HH + hh]) + erh + __ldg(&g_ee[tp * HH + hh]);
        x = x > 0.f ? x : SLOPE * x;
        float w = __expf(x) * rs;
        if ((lane & 7) == 0) {
            int e = __ldg(&g_eids[off + i]);
            out_a[(size_t)e * HH + hh] = w;
        }
        uint4 v = __ldg((const uint4*)(g_feat_h + (size_t)sv * HF + co));
        const __half2* h = (const __half2*)&v;
#pragma unroll
        for (int u = 0; u < 4; u++) {
            float2 f = __half22float2(h[u]);
            a[2 * u]     += w * f.x;
            a[2 * u + 1] += w * f.y;
        }
    }

    float4* op = (float4*)(out_rst + (size_t)d * HF + co);
    op[0] = make_float4(a[0], a[1], a[2], a[3]);
    op[1] = make_float4(a[4], a[5], a[6], a[7]);
}

// ---------------- launch ------------------------------------------------------
extern "C" void kernel_launch(void* const* d_in, const int* in_sizes, int n_in,
                              void* d_out, int out_size)
{
    const float* nfeat    = (const float*)d_in[0];
    const float* fc_w     = (const float*)d_in[1];
    const float* fc_e_w   = (const float*)d_in[2];
    const float* attn_l   = (const float*)d_in[3];
    const float* attn_r   = (const float*)d_in[4];
    const float* attn_e   = (const float*)d_in[5];
    const float* edge_emb = (const float*)d_in[6];
    const int*   src      = (const int*)d_in[7];
    const int*   dst      = (const int*)d_in[8];
    const int*   etype    = (const int*)d_in[9];

    float* out_rst = (float*)d_out;
    float* out_a   = (float*)d_out + (size_t)NN * HF;

    __half* feat_ptr;
    float *el_ptr, *er_ptr;
    int *cnt_ptr;
    cudaGetSymbolAddress((void**)&feat_ptr, g_feat_h);
    cudaGetSymbolAddress((void**)&el_ptr, g_el);
    cudaGetSymbolAddress((void**)&er_ptr, g_er);
    cudaGetSymbolAddress((void**)&cnt_ptr, g_cnt);

    static cudaStream_t s1 = nullptr, s2 = nullptr;
    static cudaEvent_t evA = nullptr, evB = nullptr, evE = nullptr;
    if (!s1) {
        cudaStreamCreateWithFlags(&s1, cudaStreamNonBlocking);
        cudaStreamCreateWithFlags(&s2, cudaStreamNonBlocking);
        cudaEventCreateWithFlags(&evA, cudaEventDisableTiming);
        cudaEventCreateWithFlags(&evB, cudaEventDisableTiming);
        cudaEventCreateWithFlags(&evE, cudaEventDisableTiming);
        cudaFuncSetAttribute(gemm_mma_kernel,
                             cudaFuncAttributeMaxDynamicSharedMemorySize, GEMM_SMEM);
    }

    // fork from capture-origin stream
    cudaEventRecord(evA, 0);
    cudaStreamWaitEvent(s1, evA, 0);
    cudaStreamWaitEvent(s2, evA, 0);

    // s1: projection path
    cudaMemsetAsync(el_ptr, 0, NN * HH * sizeof(float), s1);
    cudaMemsetAsync(er_ptr, 0, NN * HH * sizeof(float), s1);
    convert_b_kernel<<<(IND * HF / 4 + 255) / 256, 256, 0, s1>>>(fc_w);
    {
        dim3 grid((NN + BM - 1) / BM, HF / BN);
        gemm_mma_kernel<<<grid, 256, GEMM_SMEM, s1>>>(nfeat, feat_ptr, attn_l, attn_r, NN);
    }

    // s2: CSR ids path (independent of GEMM, fully concurrent)
    cudaMemsetAsync(cnt_ptr, 0, (NN + 1) * sizeof(int), s2);
    count_kernel<<<(EE + 255) / 256, 256, 0, s2>>>(dst);
    scan1_kernel<<<NSCAN, SCAN_B, 0, s2>>>();
    scan2_kernel<<<1, 32, 0, s2>>>();
    scan3_kernel<<<(NN + 256) / 256, 256, 0, s2>>>();
    scatter_ids_kernel<<<(EE + 255) / 256, 256, 0, s2>>>(src, dst, etype);
    ee_kernel<<<1, 32, 0, s2>>>(edge_emb, fc_e_w, attn_e);

    // join: fused aggregate needs GEMM (feat, el, er) + CSR ids + ee
    cudaEventRecord(evB, s2);
    cudaStreamWaitEvent(s1, evB, 0);
    aggregate_kernel<<<(NN + 7) / 8, 256, 0, s1>>>(out_rst, out_a);

    // join back to origin
    cudaEventRecord(evE, s1);
    cudaStreamWaitEvent(0, evE, 0);
}

// round 16
// speedup vs baseline: 1.0387x; 1.0387x over previous
#include <cuda_runtime.h>
#include <cuda_bf16.h>
#include <cuda_fp16.h>
#include <math.h>
#include <stdint.h>

// Problem constants
#define NN   50000
#define EE   800000
#define IND  256
#define HH   4
#define FF   64
#define HF   256
#define EFD  64
#define NT   8
#define SLOPE 0.2f

// ---------------- scratch ----------------------------------------------------
__device__ __half g_feat_h[NN * HF];          // fp16 feat (gather payload)
__device__ float g_el[NN * HH];
__device__ float g_er[NN * HH];
__device__ float g_ee[NT * HH];
__device__ float g_sum[NN * HH];
__device__ float g_score[(size_t)EE * HH];    // exp(score), CSR order
__device__ int   g_srcs[EE];
__device__ __nv_bfloat16 g_B1[IND * HF];
__device__ __nv_bfloat16 g_B2[IND * HF];
__device__ int   g_cnt[NN + 1];
__device__ int   g_off[NN + 1];
__device__ int   g_cursor[NN];
__device__ int   g_bsum[64];
__device__ int   g_bpre[65];

// ---------------- helpers -----------------------------------------------------
__device__ __forceinline__ uint32_t smem_u32(const void* p) {
    uint32_t a;
    asm("{ .reg .u64 t; cvta.to.shared.u64 t, %1; cvt.u32.u64 %0, t; }"
        : "=r"(a) : "l"(p));
    return a;
}
__device__ __forceinline__ void ldmatrix_x4(uint32_t* r, uint32_t addr) {
    asm volatile("ldmatrix.sync.aligned.m8n8.x4.shared.b16 {%0,%1,%2,%3}, [%4];"
                 : "=r"(r[0]), "=r"(r[1]), "=r"(r[2]), "=r"(r[3]) : "r"(addr));
}
__device__ __forceinline__ void ldmatrix_x4_t(uint32_t* r, uint32_t addr) {
    asm volatile("ldmatrix.sync.aligned.m8n8.x4.trans.shared.b16 {%0,%1,%2,%3}, [%4];"
                 : "=r"(r[0]), "=r"(r[1]), "=r"(r[2]), "=r"(r[3]) : "r"(addr));
}
__device__ __forceinline__ void mma_bf16(float* c, const uint32_t* a,
                                         uint32_t b0, uint32_t b1) {
    asm volatile(
        "mma.sync.aligned.m16n8k16.row.col.f32.bf16.bf16.f32 "
        "{%0,%1,%2,%3}, {%4,%5,%6,%7}, {%8,%9}, {%0,%1,%2,%3};"
        : "+f"(c[0]), "+f"(c[1]), "+f"(c[2]), "+f"(c[3])
        : "r"(a[0]), "r"(a[1]), "r"(a[2]), "r"(a[3]), "r"(b0), "r"(b1));
}
__device__ __forceinline__ uint32_t pack_hi(float a, float b) {
    return ((uint32_t)__bfloat16_as_ushort(__float2bfloat16_rn(b)) << 16) |
           (uint32_t)__bfloat16_as_ushort(__float2bfloat16_rn(a));
}
__device__ __forceinline__ uint32_t pack_lo(float a, float b) {
    float ar = a - __bfloat162float(__float2bfloat16_rn(a));
    float br = b - __bfloat162float(__float2bfloat16_rn(b));
    return ((uint32_t)__bfloat16_as_ushort(__float2bfloat16_rn(br)) << 16) |
           (uint32_t)__bfloat16_as_ushort(__float2bfloat16_rn(ar));
}

// ---------------- B pre-conversion ------------------------------------------
__global__ void convert_b_kernel(const float* __restrict__ Bw)
{
    int i = (blockIdx.x * blockDim.x + threadIdx.x) * 4;
    float4 v = *(const float4*)(Bw + i);
    float f[4] = { v.x, v.y, v.z, v.w };
#pragma unroll
    for (int q = 0; q < 4; q++) {
        __nv_bfloat16 h = __float2bfloat16_rn(f[q]);
        g_B1[i + q] = h;
        g_B2[i + q] = __float2bfloat16_rn(f[q] - __bfloat162float(h));
    }
}

// ---------------- bf16-split GEMM, double-buffered smem, fused el/er ---------
#define BM 128
#define BN 128
#define BK 32
#define AST 40
#define BST 136
#define STG_A1 0
#define STG_A2 10240
#define STG_B1 20480
#define STG_B2 29184
#define STG_SZ 37888
#define GEMM_SMEM (2 * STG_SZ)

__global__ void __launch_bounds__(256, 2)
gemm_mma_kernel(const float* __restrict__ A, __half* __restrict__ C,
                const float* __restrict__ attn_l, const float* __restrict__ attn_r,
                int M)
{
    extern __shared__ __align__(16) char dynsm[];

    const int tid  = threadIdx.x;
    const int lane = tid & 31;
    const int wid  = tid >> 5;
    const int m0 = blockIdx.x * BM;
    const int n0 = blockIdx.y * BN;

    const int wm = (wid & 1) * 64;
    const int wn = (wid >> 1) * 32;

    float acc[4][4][4];
#pragma unroll
    for (int i = 0; i < 4; i++)
#pragma unroll
        for (int j = 0; j < 4; j++)
#pragma unroll
            for (int r = 0; r < 4; r++) acc[i][j][r] = 0.f;

    const int a_row  = tid >> 1;
    const int a_colb = (tid & 1) * 16;
    const int a_gr   = m0 + a_row;
    const int b_kr  = tid >> 3;
    const int b_nb  = (tid & 7) * 16;

    const int mat  = lane >> 3;
    const int l8   = lane & 7;
    const int a_mrow = (mat & 1) * 8 + l8;
    const int a_koff = (mat >> 1) * 8;
    const int b_krow = (mat & 1) * 8 + l8;
    const int b_noff = (mat >> 1) * 8;

    const uint32_t sm0 = smem_u32(dynsm);

    float4 va[4];
    uint4 vbh[2], vbl[2];
    {
        if (a_gr < M) {
            const float4* p = (const float4*)(A + (size_t)a_gr * IND + a_colb);
#pragma unroll
            for (int q = 0; q < 4; q++) va[q] = p[q];
        } else {
#pragma unroll
            for (int q = 0; q < 4; q++) va[q] = make_float4(0, 0, 0, 0);
        }
        const uint4* p1 = (const uint4*)(g_B1 + (size_t)b_kr * HF + n0 + b_nb);
        const uint4* p2 = (const uint4*)(g_B2 + (size_t)b_kr * HF + n0 + b_nb);
        vbh[0] = p1[0]; vbh[1] = p1[1];
        vbl[0] = p2[0]; vbl[1] = p2[1];
    }

    for (int c = 0; c < IND / BK; c++) {
        char* stg = dynsm + (c & 1) * STG_SZ;
        {
            uint32_t hi[8], lo[8];
#pragma unroll
            for (int q = 0; q < 4; q++) {
                hi[2 * q]     = pack_hi(va[q].x, va[q].y);
                hi[2 * q + 1] = pack_hi(va[q].z, va[q].w);
                lo[2 * q]     = pack_lo(va[q].x, va[q].y);
                lo[2 * q + 1] = pack_lo(va[q].z, va[q].w);
            }
            char* d1 = stg + STG_A1 + (a_row * AST + a_colb) * 2;
            char* d2 = stg + STG_A2 + (a_row * AST + a_colb) * 2;
            ((uint4*)d1)[0] = make_uint4(hi[0], hi[1], hi[2], hi[3]);
            ((uint4*)d1)[1] = make_uint4(hi[4], hi[5], hi[6], hi[7]);
            ((uint4*)d2)[0] = make_uint4(lo[0], lo[1], lo[2], lo[3]);
            ((uint4*)d2)[1] = make_uint4(lo[4], lo[5], lo[6], lo[7]);
            char* e1 = stg + STG_B1 + (b_kr * BST + b_nb) * 2;
            char* e2 = stg + STG_B2 + (b_kr * BST + b_nb) * 2;
            ((uint4*)e1)[0] = vbh[0];
            ((uint4*)e1)[1] = vbh[1];
            ((uint4*)e2)[0] = vbl[0];
            ((uint4*)e2)[1] = vbl[1];
        }
        __syncthreads();

        if (c + 1 < IND / BK) {
            const int k0 = (c + 1) * BK;
            if (a_gr < M) {
                const float4* p = (const float4*)(A + (size_t)a_gr * IND + k0 + a_colb);
#pragma unroll
                for (int q = 0; q < 4; q++) va[q] = p[q];
            } else {
#pragma unroll
                for (int q = 0; q < 4; q++) va[q] = make_float4(0, 0, 0, 0);
            }
            const uint4* p1 = (const uint4*)(g_B1 + (size_t)(k0 + b_kr) * HF + n0 + b_nb);
            const uint4* p2 = (const uint4*)(g_B2 + (size_t)(k0 + b_kr) * HF + n0 + b_nb);
            vbh[0] = p1[0]; vbh[1] = p1[1];
            vbl[0] = p2[0]; vbl[1] = p2[1];
        }

        const uint32_t sa1 = sm0 + (c & 1) * STG_SZ + STG_A1;
        const uint32_t sa2 = sm0 + (c & 1) * STG_SZ + STG_A2;
        const uint32_t sb1 = sm0 + (c & 1) * STG_SZ + STG_B1;
        const uint32_t sb2 = sm0 + (c & 1) * STG_SZ + STG_B2;

#pragma unroll
        for (int kk = 0; kk < 2; kk++) {
            uint32_t a1[4][4], a2[4][4], b1[2][4], b2[2][4];
#pragma unroll
            for (int i = 0; i < 4; i++) {
                uint32_t off = ((wm + i * 16 + a_mrow) * AST + kk * 16 + a_koff) * 2;
                ldmatrix_x4(a1[i], sa1 + off);
                ldmatrix_x4(a2[i], sa2 + off);
            }
#pragma unroll
            for (int j2 = 0; j2 < 2; j2++) {
                uint32_t off = ((kk * 16 + b_krow) * BST + wn + j2 * 16 + b_noff) * 2;
                ldmatrix_x4_t(b1[j2], sb1 + off);
                ldmatrix_x4_t(b2[j2], sb2 + off);
            }
#pragma unroll
            for (int i = 0; i < 4; i++) {
#pragma unroll
                for (int j2 = 0; j2 < 2; j2++) {
                    mma_bf16(acc[i][2 * j2],     a1[i], b1[j2][0], b1[j2][1]);
                    mma_bf16(acc[i][2 * j2],     a1[i], b2[j2][0], b2[j2][1]);
                    mma_bf16(acc[i][2 * j2],     a2[i], b1[j2][0], b1[j2][1]);
                    mma_bf16(acc[i][2 * j2 + 1], a1[i], b1[j2][2], b1[j2][3]);
                    mma_bf16(acc[i][2 * j2 + 1], a1[i], b2[j2][2], b2[j2][3]);
                    mma_bf16(acc[i][2 * j2 + 1], a2[i], b1[j2][2], b1[j2][3]);
                }
            }
        }
    }

    // ---- epilogue: store C (fp16) + fused el/er (fp32)
    const int crow = lane >> 2;
    const int ccol = (lane & 3) * 2;

    float al[4][2], ar[4][2];
#pragma unroll
    for (int j = 0; j < 4; j++) {
        int c = n0 + wn + j * 8 + ccol;
        al[j][0] = attn_l[c];     al[j][1] = attn_l[c + 1];
        ar[j][0] = attn_r[c];     ar[j][1] = attn_r[c + 1];
    }
    const int head = (n0 + wn) >> 6;

#pragma unroll
    for (int i = 0; i < 4; i++) {
        int r0 = m0 + wm + i * 16 + crow;
        float pl0 = 0.f, pr0 = 0.f, pl1 = 0.f, pr1 = 0.f;
#pragma unroll
        for (int j = 0; j < 4; j++) {
            int c = n0 + wn + j * 8 + ccol;
            if (r0 < M)
                *(__half2*)(C + (size_t)r0 * HF + c) =
                    __floats2half2_rn(acc[i][j][0], acc[i][j][1]);
            if (r0 + 8 < M)
                *(__half2*)(C + (size_t)(r0 + 8) * HF + c) =
                    __floats2half2_rn(acc[i][j][2], acc[i][j][3]);
            pl0 += acc[i][j][0] * al[j][0] + acc[i][j][1] * al[j][1];
            pr0 += acc[i][j][0] * ar[j][0] + acc[i][j][1] * ar[j][1];
            pl1 += acc[i][j][2] * al[j][0] + acc[i][j][3] * al[j][1];
            pr1 += acc[i][j][2] * ar[j][0] + acc[i][j][3] * ar[j][1];
        }
#pragma unroll
        for (int o = 1; o <= 2; o <<= 1) {
            pl0 += __shfl_xor_sync(0xffffffffu, pl0, o);
            pr0 += __shfl_xor_sync(0xffffffffu, pr0, o);
            pl1 += __shfl_xor_sync(0xffffffffu, pl1, o);
            pr1 += __shfl_xor_sync(0xffffffffu, pr1, o);
        }
        if ((lane & 3) == 0) {
            if (r0 < M) {
                atomicAdd(&g_el[r0 * HH + head], pl0);
                atomicAdd(&g_er[r0 * HH + head], pr0);
            }
            if (r0 + 8 < M) {
                atomicAdd(&g_el[(r0 + 8) * HH + head], pl1);
                atomicAdd(&g_er[(r0 + 8) * HH + head], pr1);
            }
        }
    }
}

// ---------------- ee per etype ------------------------------------------------
__global__ void ee_kernel(const float* __restrict__ edge_emb,
                          const float* __restrict__ fc_e_w,
                          const float* __restrict__ attn_e)
{
    int t = threadIdx.x;
    if (t >= NT * HH) return;
    int tt = t >> 2, h = t & 3;
    float sum = 0.f;
    for (int e = 0; e < EFD; e++) {
        float ef = 0.f;
#pragma unroll 8
        for (int k = 0; k < EFD; k++)
            ef += edge_emb[tt * EFD + k] * fc_e_w[k * (HH * EFD) + h * EFD + e];
        sum += ef * attn_e[h * EFD + e];
    }
    g_ee[tt * HH + h] = sum;
}

// ---------------- CSR build ---------------------------------------------------
__global__ void count_kernel(const int* __restrict__ dst)
{
    int e = blockIdx.x * blockDim.x + threadIdx.x;
    if (e < EE) atomicAdd(&g_cnt[dst[e]], 1);
}

#define SCAN_B 1024
#define NSCAN ((NN + SCAN_B - 1) / SCAN_B)

__global__ void scan1_kernel()
{
    __shared__ int s[SCAN_B];
    int b = blockIdx.x, tid = threadIdx.x;
    int idx = b * SCAN_B + tid;
    int v = (idx < NN) ? g_cnt[idx] : 0;
    s[tid] = v;
    __syncthreads();
    for (int off = 1; off < SCAN_B; off <<= 1) {
        int tmp = (tid >= off) ? s[tid - off] : 0;
        __syncthreads();
        s[tid] += tmp;
        __syncthreads();
    }
    if (idx < NN) g_off[idx] = s[tid] - v;
    if (tid == SCAN_B - 1) g_bsum[b] = s[tid];
}

__global__ void scan2_kernel()
{
    if (threadIdx.x == 0) {
        int acc = 0;
        for (int b = 0; b < NSCAN; b++) { g_bpre[b] = acc; acc += g_bsum[b]; }
        g_bpre[NSCAN] = acc;
    }
}

__global__ void scan3_kernel()
{
    int idx = blockIdx.x * blockDim.x + threadIdx.x;
    if (idx < NN) {
        int v = g_off[idx] + g_bpre[idx >> 10];
        g_off[idx] = v;
        g_cursor[idx] = v;
    } else if (idx == NN) {
        g_off[NN] = g_bpre[NSCAN];
    }
}

// ---- scatter: CSR srcs + exp(score); NO sum atomics --------------------------
__global__ void scatter_score_kernel(const int* __restrict__ src,
                                     const int* __restrict__ dst,
                                     const int* __restrict__ etype)
{
    int e = blockIdx.x * blockDim.x + threadIdx.x;
    if (e >= EE) return;
    int dv = dst[e];
    int pos = atomicAdd(&g_cursor[dv], 1);
    int sv = src[e], tp = etype[e];
    g_srcs[pos] = sv;
    float4 l = *(const float4*)&g_el[sv * HH];
    float4 r = *(const float4*)&g_er[dv * HH];
    float4 t = *(const float4*)&g_ee[tp * HH];
    float x0 = l.x + r.x + t.x;  x0 = x0 > 0.f ? x0 : SLOPE * x0;
    float x1 = l.y + r.y + t.y;  x1 = x1 > 0.f ? x1 : SLOPE * x1;
    float x2 = l.z + r.z + t.z;  x2 = x2 > 0.f ? x2 : SLOPE * x2;
    float x3 = l.w + r.w + t.w;  x3 = x3 > 0.f ? x3 : SLOPE * x3;
    *(float4*)&g_score[(size_t)pos * HH] =
        make_float4(__expf(x0), __expf(x1), __expf(x2), __expf(x3));
}

// ---- sum: warp-per-dst reduction of CSR-ordered scores (contiguous) ----------
__global__ void __launch_bounds__(256)
sum_kernel()
{
    const int d    = blockIdx.x * 8 + (threadIdx.x >> 5);
    const int lane = threadIdx.x & 31;
    if (d >= NN) return;
    const int off = g_off[d];
    const int deg = g_off[d + 1] - off;
    const int h   = lane & 3;

    float s = 0.f;
    for (int i = lane >> 2; i < deg; i += 8)
        s += g_score[(size_t)(off + i) * HH + h];
#pragma unroll
    for (int o = 4; o <= 16; o <<= 1)
        s += __shfl_xor_sync(0xffffffffu, s, o);
    if (lane < HH) g_sum[d * HH + lane] = s;
}

// ---- out_a: edge-parallel, coalesced writes ----------------------------------
__global__ void out_a_kernel(const int* __restrict__ src,
                             const int* __restrict__ dst,
                             const int* __restrict__ etype,
                             float* __restrict__ out_a)
{
    int e = blockIdx.x * blockDim.x + threadIdx.x;
    if (e >= EE) return;
    int sv = src[e], dv = dst[e], tp = etype[e];
    float4 l = *(const float4*)&g_el[sv * HH];
    float4 r = *(const float4*)&g_er[dv * HH];
    float4 t = *(const float4*)&g_ee[tp * HH];
    float4 s = *(const float4*)&g_sum[dv * HH];
    float x0 = l.x + r.x + t.x;  x0 = x0 > 0.f ? x0 : SLOPE * x0;
    float x1 = l.y + r.y + t.y;  x1 = x1 > 0.f ? x1 : SLOPE * x1;
    float x2 = l.z + r.z + t.z;  x2 = x2 > 0.f ? x2 : SLOPE * x2;
    float x3 = l.w + r.w + t.w;  x3 = x3 > 0.f ? x3 : SLOPE * x3;
    float4 w;
    w.x = __expf(x0) * (1.f / s.x);
    w.y = __expf(x1) * (1.f / s.y);
    w.z = __expf(x2) * (1.f / s.z);
    w.w = __expf(x3) * (1.f / s.w);
    *(float4*)&out_a[(size_t)e * HH] = w;
}

// ---------------- warp-per-dst aggregation, fp16 gather, unroll-2 --------------
__global__ void __launch_bounds__(256)
aggregate_kernel(float* __restrict__ out_rst)
{
    const int d    = blockIdx.x * 8 + (threadIdx.x >> 5);
    const int lane = threadIdx.x & 31;
    if (d >= NN) return;

    const int off = g_off[d];
    const int deg = g_off[d + 1] - off;
    const int hh  = lane >> 3;
    const int co  = lane * 8;            // 8 halves = 16 B per lane

    float a[8];
#pragma unroll
    for (int q = 0; q < 8; q++) a[q] = 0.f;

    if (deg > 0) {
        const float rs = 1.f / g_sum[d * HH + hh];
        int i = 0;
        for (; i + 2 <= deg; i += 2) {
            int   sv0 = __ldg(&g_srcs[off + i]);
            int   sv1 = __ldg(&g_srcs[off + i + 1]);
            float w0  = __ldg(&g_score[(size_t)(off + i) * HH + hh]) * rs;
            float w1  = __ldg(&g_score[(size_t)(off + i + 1) * HH + hh]) * rs;
            uint4 v0 = __ldg((const uint4*)(g_feat_h + (size_t)sv0 * HF + co));
            uint4 v1 = __ldg((const uint4*)(g_feat_h + (size_t)sv1 * HF + co));
            const __half2* h0 = (const __half2*)&v0;
            const __half2* h1 = (const __half2*)&v1;
#pragma unroll
            for (int u = 0; u < 4; u++) {
                float2 f0 = __half22float2(h0[u]);
                float2 f1 = __half22float2(h1[u]);
                a[2 * u]     += w0 * f0.x + w1 * f1.x;
                a[2 * u + 1] += w0 * f0.y + w1 * f1.y;
            }
        }
        if (i < deg) {
            int   sv = __ldg(&g_srcs[off + i]);
            float w  = __ldg(&g_score[(size_t)(off + i) * HH + hh]) * rs;
            uint4 v = __ldg((const uint4*)(g_feat_h + (size_t)sv * HF + co));
            const __half2* h = (const __half2*)&v;
#pragma unroll
            for (int u = 0; u < 4; u++) {
                float2 f = __half22float2(h[u]);
                a[2 * u]     += w * f.x;
                a[2 * u + 1] += w * f.y;
            }
        }
    }

    float4* op = (float4*)(out_rst + (size_t)d * HF + co);
    op[0] = make_float4(a[0], a[1], a[2], a[3]);
    op[1] = make_float4(a[4], a[5], a[6], a[7]);
}

// ---------------- launch ------------------------------------------------------
extern "C" void kernel_launch(void* const* d_in, const int* in_sizes, int n_in,
                              void* d_out, int out_size)
{
    const float* nfeat    = (const float*)d_in[0];
    const float* fc_w     = (const float*)d_in[1];
    const float* fc_e_w   = (const float*)d_in[2];
    const float* attn_l   = (const float*)d_in[3];
    const float* attn_r   = (const float*)d_in[4];
    const float* attn_e   = (const float*)d_in[5];
    const float* edge_emb = (const float*)d_in[6];
    const int*   src      = (const int*)d_in[7];
    const int*   dst      = (const int*)d_in[8];
    const int*   etype    = (const int*)d_in[9];

    float* out_rst = (float*)d_out;
    float* out_a   = (float*)d_out + (size_t)NN * HF;

    __half* feat_ptr;
    float *el_ptr, *er_ptr;
    int *cnt_ptr;
    cudaGetSymbolAddress((void**)&feat_ptr, g_feat_h);
    cudaGetSymbolAddress((void**)&el_ptr, g_el);
    cudaGetSymbolAddress((void**)&er_ptr, g_er);
    cudaGetSymbolAddress((void**)&cnt_ptr, g_cnt);

    static cudaStream_t s1 = nullptr, s2 = nullptr;
    static cudaEvent_t evA = nullptr, evB = nullptr, evC = nullptr,
                       evD = nullptr, evE = nullptr;
    if (!s1) {
        cudaStreamCreateWithFlags(&s1, cudaStreamNonBlocking);
        cudaStreamCreateWithFlags(&s2, cudaStreamNonBlocking);
        cudaEventCreateWithFlags(&evA, cudaEventDisableTiming);
        cudaEventCreateWithFlags(&evB, cudaEventDisableTiming);
        cudaEventCreateWithFlags(&evC, cudaEventDisableTiming);
        cudaEventCreateWithFlags(&evD, cudaEventDisableTiming);
        cudaEventCreateWithFlags(&evE, cudaEventDisableTiming);
        cudaFuncSetAttribute(gemm_mma_kernel,
                             cudaFuncAttributeMaxDynamicSharedMemorySize, GEMM_SMEM);
    }

    // fork from capture-origin stream
    cudaEventRecord(evA, 0);
    cudaStreamWaitEvent(s1, evA, 0);
    cudaStreamWaitEvent(s2, evA, 0);

    // s1: projection path
    cudaMemsetAsync(el_ptr, 0, NN * HH * sizeof(float), s1);
    cudaMemsetAsync(er_ptr, 0, NN * HH * sizeof(float), s1);
    convert_b_kernel<<<(IND * HF / 4 + 255) / 256, 256, 0, s1>>>(fc_w);
    {
        dim3 grid((NN + BM - 1) / BM, HF / BN);
        gemm_mma_kernel<<<grid, 256, GEMM_SMEM, s1>>>(nfeat, feat_ptr, attn_l, attn_r, NN);
    }

    // s2: CSR path (independent of GEMM)
    cudaMemsetAsync(cnt_ptr, 0, (NN + 1) * sizeof(int), s2);
    count_kernel<<<(EE + 255) / 256, 256, 0, s2>>>(dst);
    scan1_kernel<<<NSCAN, SCAN_B, 0, s2>>>();
    scan2_kernel<<<1, 32, 0, s2>>>();
    scan3_kernel<<<(NN + 256) / 256, 256, 0, s2>>>();
    ee_kernel<<<1, 32, 0, s2>>>(edge_emb, fc_e_w, attn_e);

    // join: scatter needs both paths
    cudaEventRecord(evB, s2);
    cudaStreamWaitEvent(s1, evB, 0);
    scatter_score_kernel<<<(EE + 255) / 256, 256, 0, s1>>>(src, dst, etype);
    sum_kernel<<<(NN + 7) / 8, 256, 0, s1>>>();

    // fork: out_a (s2) concurrent with aggregate (s1)
    cudaEventRecord(evC, s1);
    cudaStreamWaitEvent(s2, evC, 0);
    out_a_kernel<<<(EE + 255) / 256, 256, 0, s2>>>(src, dst, etype, out_a);
    aggregate_kernel<<<(NN + 7) / 8, 256, 0, s1>>>(out_rst);

    // join back to origin
    cudaEventRecord(evD, s2);
    cudaStreamWaitEvent(s1, evD, 0);
    cudaEventRecord(evE, s1);
    cudaStreamWaitEvent(0, evE, 0);
}

// round 17
// speedup vs baseline: 1.1966x; 1.1520x over previous
#include <cuda_runtime.h>
#include <cuda_bf16.h>
#include <cuda_fp16.h>
#include <math.h>
#include <stdint.h>

// Problem constants
#define NN   50000
#define EE   800000
#define IND  256
#define HH   4
#define FF   64
#define HF   256
#define EFD  64
#define NT   8
#define SLOPE 0.2f

// ---------------- scratch ----------------------------------------------------
__device__ __half g_feat_h[NN * HF];          // fp16 feat (gather payload)
__device__ float g_el[NN * HH];
__device__ float g_er[NN * HH];
__device__ float g_ee[NT * HH];
__device__ float g_W[IND * 8];                // fc_w @ [attn_l | attn_r]
__device__ float g_sum[NN * HH];
__device__ float g_score[(size_t)EE * HH];    // exp(score), CSR order
__device__ int   g_srcs[EE];
__device__ __nv_bfloat16 g_B1[IND * HF];
__device__ __nv_bfloat16 g_B2[IND * HF];
__device__ int   g_cnt[NN + 1];
__device__ int   g_off[NN + 1];
__device__ int   g_cursor[NN];
__device__ int   g_bsum[64];
__device__ int   g_bpre[65];

// ---------------- helpers -----------------------------------------------------
__device__ __forceinline__ uint32_t smem_u32(const void* p) {
    uint32_t a;
    asm("{ .reg .u64 t; cvta.to.shared.u64 t, %1; cvt.u32.u64 %0, t; }"
        : "=r"(a) : "l"(p));
    return a;
}
__device__ __forceinline__ void ldmatrix_x4(uint32_t* r, uint32_t addr) {
    asm volatile("ldmatrix.sync.aligned.m8n8.x4.shared.b16 {%0,%1,%2,%3}, [%4];"
                 : "=r"(r[0]), "=r"(r[1]), "=r"(r[2]), "=r"(r[3]) : "r"(addr));
}
__device__ __forceinline__ void ldmatrix_x4_t(uint32_t* r, uint32_t addr) {
    asm volatile("ldmatrix.sync.aligned.m8n8.x4.trans.shared.b16 {%0,%1,%2,%3}, [%4];"
                 : "=r"(r[0]), "=r"(r[1]), "=r"(r[2]), "=r"(r[3]) : "r"(addr));
}
__device__ __forceinline__ void mma_bf16(float* c, const uint32_t* a,
                                         uint32_t b0, uint32_t b1) {
    asm volatile(
        "mma.sync.aligned.m16n8k16.row.col.f32.bf16.bf16.f32 "
        "{%0,%1,%2,%3}, {%4,%5,%6,%7}, {%8,%9}, {%0,%1,%2,%3};"
        : "+f"(c[0]), "+f"(c[1]), "+f"(c[2]), "+f"(c[3])
        : "r"(a[0]), "r"(a[1]), "r"(a[2]), "r"(a[3]), "r"(b0), "r"(b1));
}
__device__ __forceinline__ uint32_t pack_hi(float a, float b) {
    return ((uint32_t)__bfloat16_as_ushort(__float2bfloat16_rn(b)) << 16) |
           (uint32_t)__bfloat16_as_ushort(__float2bfloat16_rn(a));
}
__device__ __forceinline__ uint32_t pack_lo(float a, float b) {
    float ar = a - __bfloat162float(__float2bfloat16_rn(a));
    float br = b - __bfloat162float(__float2bfloat16_rn(b));
    return ((uint32_t)__bfloat16_as_ushort(__float2bfloat16_rn(br)) << 16) |
           (uint32_t)__bfloat16_as_ushort(__float2bfloat16_rn(ar));
}

// ---------------- B pre-conversion ------------------------------------------
__global__ void convert_b_kernel(const float* __restrict__ Bw)
{
    int i = (blockIdx.x * blockDim.x + threadIdx.x) * 4;
    float4 v = *(const float4*)(Bw + i);
    float f[4] = { v.x, v.y, v.z, v.w };
#pragma unroll
    for (int q = 0; q < 4; q++) {
        __nv_bfloat16 h = __float2bfloat16_rn(f[q]);
        g_B1[i + q] = h;
        g_B2[i + q] = __float2bfloat16_rn(f[q] - __bfloat162float(h));
    }
}

// ---------------- W = fc_w @ [attn_l | attn_r]  (256x8) -----------------------
__global__ void wl_kernel(const float* __restrict__ fc_w,
                          const float* __restrict__ attn_l,
                          const float* __restrict__ attn_r)
{
    int k = threadIdx.x;                 // 0..255
    const float* row = fc_w + (size_t)k * HF;
#pragma unroll
    for (int h = 0; h < HH; h++) {
        float sl = 0.f, sr = 0.f;
#pragma unroll 16
        for (int f = 0; f < FF; f++) {
            float w = row[h * FF + f];
            sl += w * attn_l[h * FF + f];
            sr += w * attn_r[h * FF + f];
        }
        g_W[k * 8 + h]     = sl;
        g_W[k * 8 + 4 + h] = sr;
    }
}

// ---------------- el/er skinny GEMM: nfeat @ W --------------------------------
__global__ void __launch_bounds__(256)
elr_lite_kernel(const float* __restrict__ nfeat)
{
    __shared__ float tile[32][257];
    __shared__ float Wsh[IND * 8];

    const int tid = threadIdx.x;
    const int n0  = blockIdx.x * 32;

    ((float4*)Wsh)[tid * 2]     = ((const float4*)g_W)[tid * 2];
    ((float4*)Wsh)[tid * 2 + 1] = ((const float4*)g_W)[tid * 2 + 1];

#pragma unroll
    for (int j = 0; j < 8; j++) {
        int idx = tid + j * 256;
        int row = idx >> 6, c4 = idx & 63;
        int n = n0 + row;
        float4 v = (n < NN) ? ((const float4*)(nfeat + (size_t)n * IND))[c4]
                            : make_float4(0.f, 0.f, 0.f, 0.f);
        float* d = &tile[row][c4 * 4];
        d[0] = v.x; d[1] = v.y; d[2] = v.z; d[3] = v.w;
    }
    __syncthreads();

    const int nd = tid >> 3;
    const int h  = tid & 7;
    const int n  = n0 + nd;
    float acc = 0.f;
#pragma unroll 16
    for (int k = 0; k < IND; k++)
        acc += tile[nd][k] * Wsh[k * 8 + h];
    if (n < NN) {
        if (h < HH) g_el[n * HH + h] = acc;
        else        g_er[n * HH + (h - HH)] = acc;
    }
}

// ---------------- bf16-split GEMM, double-buffered smem, fp16 out -------------
#define BM 128
#define BN 128
#define BK 32
#define AST 40
#define BST 136
#define STG_A1 0
#define STG_A2 10240
#define STG_B1 20480
#define STG_B2 29184
#define STG_SZ 37888
#define GEMM_SMEM (2 * STG_SZ)

__global__ void __launch_bounds__(256, 2)
gemm_mma_kernel(const float* __restrict__ A, __half* __restrict__ C, int M)
{
    extern __shared__ __align__(16) char dynsm[];

    const int tid  = threadIdx.x;
    const int lane = tid & 31;
    const int wid  = tid >> 5;
    const int m0 = blockIdx.x * BM;
    const int n0 = blockIdx.y * BN;

    const int wm = (wid & 1) * 64;
    const int wn = (wid >> 1) * 32;

    float acc[4][4][4];
#pragma unroll
    for (int i = 0; i < 4; i++)
#pragma unroll
        for (int j = 0; j < 4; j++)
#pragma unroll
            for (int r = 0; r < 4; r++) acc[i][j][r] = 0.f;

    const int a_row  = tid >> 1;
    const int a_colb = (tid & 1) * 16;
    const int a_gr   = m0 + a_row;
    const int b_kr  = tid >> 3;
    const int b_nb  = (tid & 7) * 16;

    const int mat  = lane >> 3;
    const int l8   = lane & 7;
    const int a_mrow = (mat & 1) * 8 + l8;
    const int a_koff = (mat >> 1) * 8;
    const int b_krow = (mat & 1) * 8 + l8;
    const int b_noff = (mat >> 1) * 8;

    const uint32_t sm0 = smem_u32(dynsm);

    float4 va[4];
    uint4 vbh[2], vbl[2];
    {
        if (a_gr < M) {
            const float4* p = (const float4*)(A + (size_t)a_gr * IND + a_colb);
#pragma unroll
            for (int q = 0; q < 4; q++) va[q] = p[q];
        } else {
#pragma unroll
            for (int q = 0; q < 4; q++) va[q] = make_float4(0, 0, 0, 0);
        }
        const uint4* p1 = (const uint4*)(g_B1 + (size_t)b_kr * HF + n0 + b_nb);
        const uint4* p2 = (const uint4*)(g_B2 + (size_t)b_kr * HF + n0 + b_nb);
        vbh[0] = p1[0]; vbh[1] = p1[1];
        vbl[0] = p2[0]; vbl[1] = p2[1];
    }

    for (int c = 0; c < IND / BK; c++) {
        char* stg = dynsm + (c & 1) * STG_SZ;
        {
            uint32_t hi[8], lo[8];
#pragma unroll
            for (int q = 0; q < 4; q++) {
                hi[2 * q]     = pack_hi(va[q].x, va[q].y);
                hi[2 * q + 1] = pack_hi(va[q].z, va[q].w);
                lo[2 * q]     = pack_lo(va[q].x, va[q].y);
                lo[2 * q + 1] = pack_lo(va[q].z, va[q].w);
            }
            char* d1 = stg + STG_A1 + (a_row * AST + a_colb) * 2;
            char* d2 = stg + STG_A2 + (a_row * AST + a_colb) * 2;
            ((uint4*)d1)[0] = make_uint4(hi[0], hi[1], hi[2], hi[3]);
            ((uint4*)d1)[1] = make_uint4(hi[4], hi[5], hi[6], hi[7]);
            ((uint4*)d2)[0] = make_uint4(lo[0], lo[1], lo[2], lo[3]);
            ((uint4*)d2)[1] = make_uint4(lo[4], lo[5], lo[6], lo[7]);
            char* e1 = stg + STG_B1 + (b_kr * BST + b_nb) * 2;
            char* e2 = stg + STG_B2 + (b_kr * BST + b_nb) * 2;
            ((uint4*)e1)[0] = vbh[0];
            ((uint4*)e1)[1] = vbh[1];
            ((uint4*)e2)[0] = vbl[0];
            ((uint4*)e2)[1] = vbl[1];
        }
        __syncthreads();

        if (c + 1 < IND / BK) {
            const int k0 = (c + 1) * BK;
            if (a_gr < M) {
                const float4* p = (const float4*)(A + (size_t)a_gr * IND + k0 + a_colb);
#pragma unroll
                for (int q = 0; q < 4; q++) va[q] = p[q];
            } else {
#pragma unroll
                for (int q = 0; q < 4; q++) va[q] = make_float4(0, 0, 0, 0);
            }
            const uint4* p1 = (const uint4*)(g_B1 + (size_t)(k0 + b_kr) * HF + n0 + b_nb);
            const uint4* p2 = (const uint4*)(g_B2 + (size_t)(k0 + b_kr) * HF + n0 + b_nb);
            vbh[0] = p1[0]; vbh[1] = p1[1];
            vbl[0] = p2[0]; vbl[1] = p2[1];
        }

        const uint32_t sa1 = sm0 + (c & 1) * STG_SZ + STG_A1;
        const uint32_t sa2 = sm0 + (c & 1) * STG_SZ + STG_A2;
        const uint32_t sb1 = sm0 + (c & 1) * STG_SZ + STG_B1;
        const uint32_t sb2 = sm0 + (c & 1) * STG_SZ + STG_B2;

#pragma unroll
        for (int kk = 0; kk < 2; kk++) {
            uint32_t a1[4][4], a2[4][4], b1[2][4], b2[2][4];
#pragma unroll
            for (int i = 0; i < 4; i++) {
                uint32_t off = ((wm + i * 16 + a_mrow) * AST + kk * 16 + a_koff) * 2;
                ldmatrix_x4(a1[i], sa1 + off);
                ldmatrix_x4(a2[i], sa2 + off);
            }
#pragma unroll
            for (int j2 = 0; j2 < 2; j2++) {
                uint32_t off = ((kk * 16 + b_krow) * BST + wn + j2 * 16 + b_noff) * 2;
                ldmatrix_x4_t(b1[j2], sb1 + off);
                ldmatrix_x4_t(b2[j2], sb2 + off);
            }
#pragma unroll
            for (int i = 0; i < 4; i++) {
#pragma unroll
                for (int j2 = 0; j2 < 2; j2++) {
                    mma_bf16(acc[i][2 * j2],     a1[i], b1[j2][0], b1[j2][1]);
                    mma_bf16(acc[i][2 * j2],     a1[i], b2[j2][0], b2[j2][1]);
                    mma_bf16(acc[i][2 * j2],     a2[i], b1[j2][0], b1[j2][1]);
                    mma_bf16(acc[i][2 * j2 + 1], a1[i], b1[j2][2], b1[j2][3]);
                    mma_bf16(acc[i][2 * j2 + 1], a1[i], b2[j2][2], b2[j2][3]);
                    mma_bf16(acc[i][2 * j2 + 1], a2[i], b1[j2][2], b1[j2][3]);
                }
            }
        }
    }

    // ---- epilogue: fp16 store only
    const int crow = lane >> 2;
    const int ccol = (lane & 3) * 2;
#pragma unroll
    for (int i = 0; i < 4; i++) {
        int r0 = m0 + wm + i * 16 + crow;
#pragma unroll
        for (int j = 0; j < 4; j++) {
            int c = n0 + wn + j * 8 + ccol;
            if (r0 < M)
                *(__half2*)(C + (size_t)r0 * HF + c) =
                    __floats2half2_rn(acc[i][j][0], acc[i][j][1]);
            if (r0 + 8 < M)
                *(__half2*)(C + (size_t)(r0 + 8) * HF + c) =
                    __floats2half2_rn(acc[i][j][2], acc[i][j][3]);
        }
    }
}

// ---------------- ee per etype ------------------------------------------------
__global__ void ee_kernel(const float* __restrict__ edge_emb,
                          const float* __restrict__ fc_e_w,
                          const float* __restrict__ attn_e)
{
    int t = threadIdx.x;
    if (t >= NT * HH) return;
    int tt = t >> 2, h = t & 3;
    float sum = 0.f;
    for (int e = 0; e < EFD; e++) {
        float ef = 0.f;
#pragma unroll 8
        for (int k = 0; k < EFD; k++)
            ef += edge_emb[tt * EFD + k] * fc_e_w[k * (HH * EFD) + h * EFD + e];
        sum += ef * attn_e[h * EFD + e];
    }
    g_ee[tt * HH + h] = sum;
}

// ---------------- CSR build ---------------------------------------------------
__global__ void count_kernel(const int* __restrict__ dst)
{
    int e = blockIdx.x * blockDim.x + threadIdx.x;
    if (e < EE) atomicAdd(&g_cnt[dst[e]], 1);
}

#define SCAN_B 1024
#define NSCAN ((NN + SCAN_B - 1) / SCAN_B)

__global__ void scan1_kernel()
{
    __shared__ int s[SCAN_B];
    int b = blockIdx.x, tid = threadIdx.x;
    int idx = b * SCAN_B + tid;
    int v = (idx < NN) ? g_cnt[idx] : 0;
    s[tid] = v;
    __syncthreads();
    for (int off = 1; off < SCAN_B; off <<= 1) {
        int tmp = (tid >= off) ? s[tid - off] : 0;
        __syncthreads();
        s[tid] += tmp;
        __syncthreads();
    }
    if (idx < NN) g_off[idx] = s[tid] - v;
    if (tid == SCAN_B - 1) g_bsum[b] = s[tid];
}

__global__ void scan2_kernel()
{
    if (threadIdx.x == 0) {
        int acc = 0;
        for (int b = 0; b < NSCAN; b++) { g_bpre[b] = acc; acc += g_bsum[b]; }
        g_bpre[NSCAN] = acc;
    }
}

__global__ void scan3_kernel()
{
    int idx = blockIdx.x * blockDim.x + threadIdx.x;
    if (idx < NN) {
        int v = g_off[idx] + g_bpre[idx >> 10];
        g_off[idx] = v;
        g_cursor[idx] = v;
    } else if (idx == NN) {
        g_off[NN] = g_bpre[NSCAN];
    }
}

// ---- scatter: CSR srcs + exp(score) ------------------------------------------
__global__ void scatter_score_kernel(const int* __restrict__ src,
                                     const int* __restrict__ dst,
                                     const int* __restrict__ etype)
{
    int e = blockIdx.x * blockDim.x + threadIdx.x;
    if (e >= EE) return;
    int dv = dst[e];
    int pos = atomicAdd(&g_cursor[dv], 1);
    int sv = src[e], tp = etype[e];
    g_srcs[pos] = sv;
    float4 l = *(const float4*)&g_el[sv * HH];
    float4 r = *(const float4*)&g_er[dv * HH];
    float4 t = *(const float4*)&g_ee[tp * HH];
    float x0 = l.x + r.x + t.x;  x0 = x0 > 0.f ? x0 : SLOPE * x0;
    float x1 = l.y + r.y + t.y;  x1 = x1 > 0.f ? x1 : SLOPE * x1;
    float x2 = l.z + r.z + t.z;  x2 = x2 > 0.f ? x2 : SLOPE * x2;
    float x3 = l.w + r.w + t.w;  x3 = x3 > 0.f ? x3 : SLOPE * x3;
    *(float4*)&g_score[(size_t)pos * HH] =
        make_float4(__expf(x0), __expf(x1), __expf(x2), __expf(x3));
}

// ---- sum: warp-per-dst reduction of CSR-ordered scores -----------------------
__global__ void __launch_bounds__(256)
sum_kernel()
{
    const int d    = blockIdx.x * 8 + (threadIdx.x >> 5);
    const int lane = threadIdx.x & 31;
    if (d >= NN) return;
    const int off = g_off[d];
    const int deg = g_off[d + 1] - off;
    const int h   = lane & 3;

    float s = 0.f;
    for (int i = lane >> 2; i < deg; i += 8)
        s += g_score[(size_t)(off + i) * HH + h];
#pragma unroll
    for (int o = 4; o <= 16; o <<= 1)
        s += __shfl_xor_sync(0xffffffffu, s, o);
    if (lane < HH) g_sum[d * HH + lane] = s;
}

// ---- out_a: edge-parallel, coalesced writes ----------------------------------
__global__ void out_a_kernel(const int* __restrict__ src,
                             const int* __restrict__ dst,
                             const int* __restrict__ etype,
                             float* __restrict__ out_a)
{
    int e = blockIdx.x * blockDim.x + threadIdx.x;
    if (e >= EE) return;
    int sv = src[e], dv = dst[e], tp = etype[e];
    float4 l = *(const float4*)&g_el[sv * HH];
    float4 r = *(const float4*)&g_er[dv * HH];
    float4 t = *(const float4*)&g_ee[tp * HH];
    float4 s = *(const float4*)&g_sum[dv * HH];
    float x0 = l.x + r.x + t.x;  x0 = x0 > 0.f ? x0 : SLOPE * x0;
    float x1 = l.y + r.y + t.y;  x1 = x1 > 0.f ? x1 : SLOPE * x1;
    float x2 = l.z + r.z + t.z;  x2 = x2 > 0.f ? x2 : SLOPE * x2;
    float x3 = l.w + r.w + t.w;  x3 = x3 > 0.f ? x3 : SLOPE * x3;
    float4 w;
    w.x = __expf(x0) * (1.f / s.x);
    w.y = __expf(x1) * (1.f / s.y);
    w.z = __expf(x2) * (1.f / s.z);
    w.w = __expf(x3) * (1.f / s.w);
    *(float4*)&out_a[(size_t)e * HH] = w;
}

// ---------------- warp-per-dst aggregation, fp16 gather, unroll-2 --------------
__global__ void __launch_bounds__(256)
aggregate_kernel(float* __restrict__ out_rst)
{
    const int d    = blockIdx.x * 8 + (threadIdx.x >> 5);
    const int lane = threadIdx.x & 31;
    if (d >= NN) return;

    const int off = g_off[d];
    const int deg = g_off[d + 1] - off;
    const int hh  = lane >> 3;
    const int co  = lane * 8;

    float a[8];
#pragma unroll
    for (int q = 0; q < 8; q++) a[q] = 0.f;

    if (deg > 0) {
        const float rs = 1.f / g_sum[d * HH + hh];
        int i = 0;
        for (; i + 2 <= deg; i += 2) {
            int   sv0 = __ldg(&g_srcs[off + i]);
            int   sv1 = __ldg(&g_srcs[off + i + 1]);
            float w0  = __ldg(&g_score[(size_t)(off + i) * HH + hh]) * rs;
            float w1  = __ldg(&g_score[(size_t)(off + i + 1) * HH + hh]) * rs;
            uint4 v0 = __ldg((const uint4*)(g_feat_h + (size_t)sv0 * HF + co));
            uint4 v1 = __ldg((const uint4*)(g_feat_h + (size_t)sv1 * HF + co));
            const __half2* h0 = (const __half2*)&v0;
            const __half2* h1 = (const __half2*)&v1;
#pragma unroll
            for (int u = 0; u < 4; u++) {
                float2 f0 = __half22float2(h0[u]);
                float2 f1 = __half22float2(h1[u]);
                a[2 * u]     += w0 * f0.x + w1 * f1.x;
                a[2 * u + 1] += w0 * f0.y + w1 * f1.y;
            }
        }
        if (i < deg) {
            int   sv = __ldg(&g_srcs[off + i]);
            float w  = __ldg(&g_score[(size_t)(off + i) * HH + hh]) * rs;
            uint4 v = __ldg((const uint4*)(g_feat_h + (size_t)sv * HF + co));
            const __half2* h = (const __half2*)&v;
#pragma unroll
            for (int u = 0; u < 4; u++) {
                float2 f = __half22float2(h[u]);
                a[2 * u]     += w * f.x;
                a[2 * u + 1] += w * f.y;
            }
        }
    }

    float4* op = (float4*)(out_rst + (size_t)d * HF + co);
    op[0] = make_float4(a[0], a[1], a[2], a[3]);
    op[1] = make_float4(a[4], a[5], a[6], a[7]);
}

// ---------------- launch ------------------------------------------------------
extern "C" void kernel_launch(void* const* d_in, const int* in_sizes, int n_in,
                              void* d_out, int out_size)
{
    const float* nfeat    = (const float*)d_in[0];
    const float* fc_w     = (const float*)d_in[1];
    const float* fc_e_w   = (const float*)d_in[2];
    const float* attn_l   = (const float*)d_in[3];
    const float* attn_r   = (const float*)d_in[4];
    const float* attn_e   = (const float*)d_in[5];
    const float* edge_emb = (const float*)d_in[6];
    const int*   src      = (const int*)d_in[7];
    const int*   dst      = (const int*)d_in[8];
    const int*   etype    = (const int*)d_in[9];

    float* out_rst = (float*)d_out;
    float* out_a   = (float*)d_out + (size_t)NN * HF;

    __half* feat_ptr;
    int *cnt_ptr;
    cudaGetSymbolAddress((void**)&feat_ptr, g_feat_h);
    cudaGetSymbolAddress((void**)&cnt_ptr, g_cnt);

    static cudaStream_t s1 = nullptr, s2 = nullptr;
    static cudaEvent_t evA = nullptr, evL = nullptr, evC = nullptr,
                       evS = nullptr, evD = nullptr, evE = nullptr;
    if (!s1) {
        cudaStreamCreateWithFlags(&s1, cudaStreamNonBlocking);
        cudaStreamCreateWithFlags(&s2, cudaStreamNonBlocking);
        cudaEventCreateWithFlags(&evA, cudaEventDisableTiming);
        cudaEventCreateWithFlags(&evL, cudaEventDisableTiming);
        cudaEventCreateWithFlags(&evC, cudaEventDisableTiming);
        cudaEventCreateWithFlags(&evS, cudaEventDisableTiming);
        cudaEventCreateWithFlags(&evD, cudaEventDisableTiming);
        cudaEventCreateWithFlags(&evE, cudaEventDisableTiming);
        cudaFuncSetAttribute(gemm_mma_kernel,
                             cudaFuncAttributeMaxDynamicSharedMemorySize, GEMM_SMEM);
    }

    // fork from capture-origin stream
    cudaEventRecord(evA, 0);
    cudaStreamWaitEvent(s1, evA, 0);
    cudaStreamWaitEvent(s2, evA, 0);

    // s1: convert_b, el/er via factorized skinny GEMM (serial, warms L2),
    //     then the big projection GEMM
    convert_b_kernel<<<(IND * HF / 4 + 255) / 256, 256, 0, s1>>>(fc_w);
    wl_kernel<<<1, 256, 0, s1>>>(fc_w, attn_l, attn_r);
    elr_lite_kernel<<<(NN + 31) / 32, 256, 0, s1>>>(nfeat);
    cudaEventRecord(evL, s1);
    {
        dim3 grid((NN + BM - 1) / BM, HF / BN);
        gemm_mma_kernel<<<grid, 256, GEMM_SMEM, s1>>>(nfeat, feat_ptr, NN);
    }

    // s2: CSR build, then (after el/er ready) the whole score chain —
    //     all inside the big GEMM's shadow
    cudaMemsetAsync(cnt_ptr, 0, (NN + 1) * sizeof(int), s2);
    count_kernel<<<(EE + 255) / 256, 256, 0, s2>>>(dst);
    scan1_kernel<<<NSCAN, SCAN_B, 0, s2>>>();
    scan2_kernel<<<1, 32, 0, s2>>>();
    scan3_kernel<<<(NN + 256) / 256, 256, 0, s2>>>();
    ee_kernel<<<1, 32, 0, s2>>>(edge_emb, fc_e_w, attn_e);
    cudaStreamWaitEvent(s2, evL, 0);
    scatter_score_kernel<<<(EE + 255) / 256, 256, 0, s2>>>(src, dst, etype);
    sum_kernel<<<(NN + 7) / 8, 256, 0, s2>>>();
    cudaEventRecord(evS, s2);
    out_a_kernel<<<(EE + 255) / 256, 256, 0, s2>>>(src, dst, etype, out_a);
    cudaEventRecord(evD, s2);

    // s1: aggregate needs GEMM (s1) + scores/sums (s2)
    cudaStreamWaitEvent(s1, evS, 0);
    aggregate_kernel<<<(NN + 7) / 8, 256, 0, s1>>>(out_rst);

    // join back to origin
    cudaStreamWaitEvent(s1, evD, 0);
    cudaEventRecord(evE, s1);
    cudaStreamWaitEvent(0, evE, 0);
}